// round 10
// baseline (speedup 1.0000x reference)
#include <cuda_runtime.h>
#include <cstdint>

// B[r,f,n] = sum_m CG[r,m] * A[f,m,n]
// f32x2 packs TWO r's per accumulator. Coefficients stream unduplicated from
// shared (1 LDS.128 = 4 coeffs = 2 FFMA2 operands); A lane-duplicated via MOVs.
// 16 r x 2 n per thread, r split in 2 groups over blockIdx.x&1.
// This round: reg diet to 64 -> 4 CTAs/SM (32 warps) for latency hiding.

using u32 = unsigned int;
using u64 = unsigned long long;

template <int M>
__global__ void __launch_bounds__(256, 4)
ace_sym_kernel(const float* __restrict__ A,
               const float* __restrict__ cg0,   // [8, M]
               const float* __restrict__ cg1,   // [24, M]
               float* __restrict__ out0,        // [8, F, 1024]
               float* __restrict__ out1,        // [24, F, 1024]
               int F)
{
    __shared__ __align__(16) float scg[M * 16];  // [m][16 local r], NOT duplicated

    const int tid   = threadIdx.x;
    const int g     = blockIdx.x & 1;        // r-group: 0 -> r 0..15, 1 -> r 16..31
    const int ntile = blockIdx.x >> 1;       // n-tile: 0 or 1
    const int rbase = g << 4;

    for (int i = tid; i < M * 16; i += 256) {
        const int m  = i >> 4;
        const int r  = i & 15;
        const int rg = rbase + r;
        scg[i] = (rg < 8) ? cg0[rg * M + m] : cg1[(rg - 8) * M + m];
    }
    __syncthreads();

    const int f  = blockIdx.y;
    const int n0 = (ntile * 256 + tid) * 2;  // 2 consecutive n per thread

    // A[f, m, n]: read as u64 pairs {a_n0, a_n1}, stride per m = 512 u64.
    const u64* __restrict__ aptr =
        reinterpret_cast<const u64*>(A + ((size_t)f * M) * 1024 + n0);

    // acc0[j] = {B[rbase+2j][n0],   B[rbase+2j+1][n0]}
    // acc1[j] = {B[rbase+2j][n0+1], B[rbase+2j+1][n0+1]}
    u64 acc0[8], acc1[8];
#pragma unroll
    for (int j = 0; j < 8; ++j) { acc0[j] = 0ull; acc1[j] = 0ull; }

    u64 ring[4];
#pragma unroll
    for (int i = 0; i < 4; ++i) ring[i] = aptr[(size_t)i * 512];

#pragma unroll 4
    for (int m = 0; m < M; ++m) {
        const u64 apair = ring[m & 3];
        if (m + 4 < M) ring[m & 3] = aptr[(size_t)(m + 4) * 512];

        const u32 ax = (u32)apair;          // a at n0
        const u32 ay = (u32)(apair >> 32);  // a at n0+1
        u64 da0, da1;                       // {a,a} duplicated for f32x2
        asm("mov.b64 %0, {%1, %1};" : "=l"(da0) : "r"(ax));
        asm("mov.b64 %0, {%1, %1};" : "=l"(da1) : "r"(ay));

        const ulonglong2* __restrict__ cp =
            reinterpret_cast<const ulonglong2*>(scg + m * 16);
#pragma unroll
        for (int q = 0; q < 4; ++q) {
            const ulonglong2 cc = cp[q];    // cc.x={c[4q],c[4q+1]} cc.y={c[4q+2],c[4q+3]}
            asm("fma.rn.f32x2 %0, %1, %2, %0;" : "+l"(acc0[2 * q])     : "l"(da0), "l"(cc.x));
            asm("fma.rn.f32x2 %0, %1, %2, %0;" : "+l"(acc1[2 * q])     : "l"(da1), "l"(cc.x));
            asm("fma.rn.f32x2 %0, %1, %2, %0;" : "+l"(acc0[2 * q + 1]) : "l"(da0), "l"(cc.y));
            asm("fma.rn.f32x2 %0, %1, %2, %0;" : "+l"(acc1[2 * q + 1]) : "l"(da1), "l"(cc.y));
        }
    }

    // Repack r-major accumulators into n-major u64s -> coalesced STG.64 streams.
    const size_t col = (size_t)f * 1024 + n0;
#pragma unroll
    for (int j = 0; j < 8; ++j) {
        const u64 s0 = (u64)(u32)acc0[j] | ((u64)(u32)acc1[j] << 32);          // row 2j:   {n0, n0+1}
        const u64 s1 = (acc0[j] >> 32)   | (acc1[j] & 0xFFFFFFFF00000000ull);  // row 2j+1: {n0, n0+1}
        const int r0 = rbase + 2 * j;
        float* p0 = (r0 < 8) ? (out0 + ((size_t)r0 * F) * 1024)
                             : (out1 + ((size_t)(r0 - 8) * F) * 1024);
        float* p1 = (r0 + 1 < 8) ? (out0 + ((size_t)(r0 + 1) * F) * 1024)
                                 : (out1 + ((size_t)(r0 + 1 - 8) * F) * 1024);
        __stcs(reinterpret_cast<long long*>(p0 + col), (long long)s0);
        __stcs(reinterpret_cast<long long*>(p1 + col), (long long)s1);
    }
}

extern "C" void kernel_launch(void* const* d_in, const int* in_sizes, int n_in,
                              void* d_out, int out_size)
{
    (void)in_sizes; (void)n_in; (void)out_size;

    const float* A2_l11  = (const float*)d_in[0];   // [1024, 9, 1024]
    const float* A2_l22  = (const float*)d_in[1];   // [1024, 25, 1024]
    const float* A2_l33  = (const float*)d_in[2];   // [1024, 49, 1024]
    const float* A3_l111 = (const float*)d_in[3];   // [512, 27, 1024]
    const float* A3_l211 = (const float*)d_in[4];   // [512, 45, 1024]

    const float* CG0_2_l11  = (const float*)d_in[5];
    const float* CG0_2_l22  = (const float*)d_in[6];
    const float* CG0_2_l33  = (const float*)d_in[7];
    const float* CG0_3_l111 = (const float*)d_in[8];
    const float* CG0_3_l211 = (const float*)d_in[9];
    const float* CG1_2_l11  = (const float*)d_in[10];
    const float* CG1_2_l22  = (const float*)d_in[11];
    const float* CG1_2_l33  = (const float*)d_in[12];
    const float* CG1_3_l111 = (const float*)d_in[13];
    const float* CG1_3_l211 = (const float*)d_in[14];

    float* out = (float*)d_out;

    // Output: b0 entries then b1 entries, each [R, F, 1024] row-major.
    float* o0_l11  = out + 0;
    float* o0_l22  = out + 8388608;     //  8*1024*1024
    float* o0_l33  = out + 16777216;
    float* o0_l111 = out + 25165824;
    float* o0_l211 = out + 29360128;    // +8*512*1024
    float* o1_l11  = out + 33554432;
    float* o1_l22  = out + 58720256;    // +24*1024*1024
    float* o1_l33  = out + 83886080;
    float* o1_l111 = out + 109051904;
    float* o1_l211 = out + 121634816;   // +24*512*1024

    const dim3 blk(256);
    // grid.x = 2 n-tiles * 2 r-groups = 4 ; grid.y = F
    ace_sym_kernel< 9><<<dim3(4, 1024), blk>>>(A2_l11,  CG0_2_l11,  CG1_2_l11,  o0_l11,  o1_l11,  1024);
    ace_sym_kernel<25><<<dim3(4, 1024), blk>>>(A2_l22,  CG0_2_l22,  CG1_2_l22,  o0_l22,  o1_l22,  1024);
    ace_sym_kernel<49><<<dim3(4, 1024), blk>>>(A2_l33,  CG0_2_l33,  CG1_2_l33,  o0_l33,  o1_l33,  1024);
    ace_sym_kernel<27><<<dim3(4,  512), blk>>>(A3_l111, CG0_3_l111, CG1_3_l111, o0_l111, o1_l111,  512);
    ace_sym_kernel<45><<<dim3(4,  512), blk>>>(A3_l211, CG0_3_l211, CG1_3_l211, o0_l211, o1_l211,  512);
}

// round 11
// speedup vs baseline: 1.5056x; 1.5056x over previous
#include <cuda_runtime.h>
#include <cstdint>

// B[r,f,n] = sum_m CG[r,m] * A[f,m,n]
// f32x2 packs TWO r's per accumulator. Coefficients stream unduplicated from
// shared (1 LDS.128 = 4 coeffs = 2 FFMA2 operands); A lane-duplicated via MOVs.
// 16 r x 2 n per thread, r split in 2 groups over blockIdx.x&1.
// occ 3 (best known); m-loop FULLY unrolled; prefetch ring deepened to 6.

using u32 = unsigned int;
using u64 = unsigned long long;

template <int M>
__global__ void __launch_bounds__(256, 3)
ace_sym_kernel(const float* __restrict__ A,
               const float* __restrict__ cg0,   // [8, M]
               const float* __restrict__ cg1,   // [24, M]
               float* __restrict__ out0,        // [8, F, 1024]
               float* __restrict__ out1,        // [24, F, 1024]
               int F)
{
    __shared__ __align__(16) float scg[M * 16];  // [m][16 local r], NOT duplicated

    const int tid   = threadIdx.x;
    const int g     = blockIdx.x & 1;        // r-group: 0 -> r 0..15, 1 -> r 16..31
    const int ntile = blockIdx.x >> 1;       // n-tile: 0 or 1
    const int rbase = g << 4;

    for (int i = tid; i < M * 16; i += 256) {
        const int m  = i >> 4;
        const int r  = i & 15;
        const int rg = rbase + r;
        scg[i] = (rg < 8) ? cg0[rg * M + m] : cg1[(rg - 8) * M + m];
    }
    __syncthreads();

    const int f  = blockIdx.y;
    const int n0 = (ntile * 256 + tid) * 2;  // 2 consecutive n per thread

    // A[f, m, n]: read as u64 pairs {a_n0, a_n1}, stride per m = 512 u64.
    const u64* __restrict__ aptr =
        reinterpret_cast<const u64*>(A + ((size_t)f * M) * 1024 + n0);

    // acc0[j] = {B[rbase+2j][n0],   B[rbase+2j+1][n0]}
    // acc1[j] = {B[rbase+2j][n0+1], B[rbase+2j+1][n0+1]}
    u64 acc0[8], acc1[8];
#pragma unroll
    for (int j = 0; j < 8; ++j) { acc0[j] = 0ull; acc1[j] = 0ull; }

    constexpr int DEPTH = 6;                 // prefetch ring depth (M >= 9 > DEPTH... ok)
    u64 ring[DEPTH];
#pragma unroll
    for (int i = 0; i < DEPTH; ++i) ring[i] = aptr[(size_t)i * 512];

#pragma unroll
    for (int m = 0; m < M; ++m) {
        const u64 apair = ring[m % DEPTH];   // compile-time index (full unroll)
        if (m + DEPTH < M) ring[m % DEPTH] = aptr[(size_t)(m + DEPTH) * 512];

        const u32 ax = (u32)apair;           // a at n0
        const u32 ay = (u32)(apair >> 32);   // a at n0+1
        u64 da0, da1;                        // {a,a} duplicated for f32x2
        asm("mov.b64 %0, {%1, %1};" : "=l"(da0) : "r"(ax));
        asm("mov.b64 %0, {%1, %1};" : "=l"(da1) : "r"(ay));

        const ulonglong2* __restrict__ cp =
            reinterpret_cast<const ulonglong2*>(scg + m * 16);
#pragma unroll
        for (int q = 0; q < 4; ++q) {
            const ulonglong2 cc = cp[q];     // cc.x={c[4q],c[4q+1]} cc.y={c[4q+2],c[4q+3]}
            asm("fma.rn.f32x2 %0, %1, %2, %0;" : "+l"(acc0[2 * q])     : "l"(da0), "l"(cc.x));
            asm("fma.rn.f32x2 %0, %1, %2, %0;" : "+l"(acc1[2 * q])     : "l"(da1), "l"(cc.x));
            asm("fma.rn.f32x2 %0, %1, %2, %0;" : "+l"(acc0[2 * q + 1]) : "l"(da0), "l"(cc.y));
            asm("fma.rn.f32x2 %0, %1, %2, %0;" : "+l"(acc1[2 * q + 1]) : "l"(da1), "l"(cc.y));
        }
    }

    // Repack r-major accumulators into n-major u64s -> coalesced STG.64 streams.
    const size_t col = (size_t)f * 1024 + n0;
#pragma unroll
    for (int j = 0; j < 8; ++j) {
        const u64 s0 = (u64)(u32)acc0[j] | ((u64)(u32)acc1[j] << 32);          // row 2j:   {n0, n0+1}
        const u64 s1 = (acc0[j] >> 32)   | (acc1[j] & 0xFFFFFFFF00000000ull);  // row 2j+1: {n0, n0+1}
        const int r0 = rbase + 2 * j;
        float* p0 = (r0 < 8) ? (out0 + ((size_t)r0 * F) * 1024)
                             : (out1 + ((size_t)(r0 - 8) * F) * 1024);
        float* p1 = (r0 + 1 < 8) ? (out0 + ((size_t)(r0 + 1) * F) * 1024)
                                 : (out1 + ((size_t)(r0 + 1 - 8) * F) * 1024);
        __stcs(reinterpret_cast<long long*>(p0 + col), (long long)s0);
        __stcs(reinterpret_cast<long long*>(p1 + col), (long long)s1);
    }
}

extern "C" void kernel_launch(void* const* d_in, const int* in_sizes, int n_in,
                              void* d_out, int out_size)
{
    (void)in_sizes; (void)n_in; (void)out_size;

    const float* A2_l11  = (const float*)d_in[0];   // [1024, 9, 1024]
    const float* A2_l22  = (const float*)d_in[1];   // [1024, 25, 1024]
    const float* A2_l33  = (const float*)d_in[2];   // [1024, 49, 1024]
    const float* A3_l111 = (const float*)d_in[3];   // [512, 27, 1024]
    const float* A3_l211 = (const float*)d_in[4];   // [512, 45, 1024]

    const float* CG0_2_l11  = (const float*)d_in[5];
    const float* CG0_2_l22  = (const float*)d_in[6];
    const float* CG0_2_l33  = (const float*)d_in[7];
    const float* CG0_3_l111 = (const float*)d_in[8];
    const float* CG0_3_l211 = (const float*)d_in[9];
    const float* CG1_2_l11  = (const float*)d_in[10];
    const float* CG1_2_l22  = (const float*)d_in[11];
    const float* CG1_2_l33  = (const float*)d_in[12];
    const float* CG1_3_l111 = (const float*)d_in[13];
    const float* CG1_3_l211 = (const float*)d_in[14];

    float* out = (float*)d_out;

    // Output: b0 entries then b1 entries, each [R, F, 1024] row-major.
    float* o0_l11  = out + 0;
    float* o0_l22  = out + 8388608;     //  8*1024*1024
    float* o0_l33  = out + 16777216;
    float* o0_l111 = out + 25165824;
    float* o0_l211 = out + 29360128;    // +8*512*1024
    float* o1_l11  = out + 33554432;
    float* o1_l22  = out + 58720256;    // +24*1024*1024
    float* o1_l33  = out + 83886080;
    float* o1_l111 = out + 109051904;
    float* o1_l211 = out + 121634816;   // +24*512*1024

    const dim3 blk(256);
    // grid.x = 2 n-tiles * 2 r-groups = 4 ; grid.y = F
    ace_sym_kernel< 9><<<dim3(4, 1024), blk>>>(A2_l11,  CG0_2_l11,  CG1_2_l11,  o0_l11,  o1_l11,  1024);
    ace_sym_kernel<25><<<dim3(4, 1024), blk>>>(A2_l22,  CG0_2_l22,  CG1_2_l22,  o0_l22,  o1_l22,  1024);
    ace_sym_kernel<49><<<dim3(4, 1024), blk>>>(A2_l33,  CG0_2_l33,  CG1_2_l33,  o0_l33,  o1_l33,  1024);
    ace_sym_kernel<27><<<dim3(4,  512), blk>>>(A3_l111, CG0_3_l111, CG1_3_l111, o0_l111, o1_l111,  512);
    ace_sym_kernel<45><<<dim3(4,  512), blk>>>(A3_l211, CG0_3_l211, CG1_3_l211, o0_l211, o1_l211,  512);
}